// round 1
// baseline (speedup 1.0000x reference)
#include <cuda_runtime.h>
#include <math.h>

// Problem constants (shapes fixed by the dataset)
#define S_TOK   16384
#define C_DIM   1280
#define C3      3840
#define D_HEAD  80
#define H_HEADS 16
#define BLK     16
#define NBLK    (S_TOK / BLK)   // 1024

// Scratch (allocation-free rule: __device__ globals)
__device__ float g_qkv[(size_t)S_TOK * C3];   // 252 MB, permuted-order QKV
__device__ float g_y  [(size_t)S_TOK * C_DIM]; // 84 MB, attention out in ORIGINAL order

// ============================================================================
// SGEMM: C[M,N] = A[M,K] @ B[K,N], fp32, 128x128x16 tiles, 256 thr, 8x8/thread
// GATHER: logical A row m reads physical row gidx[m] (fuses window permutation)
// ============================================================================
#define BM 128
#define BN 128
#define BK 16
#define TM 8
#define TN 8

template<bool GATHER>
__global__ __launch_bounds__(256, 2)
void sgemm_kernel(const float* __restrict__ A, const float* __restrict__ B,
                  float* __restrict__ C, const int* __restrict__ gidx,
                  int M, int N, int K)
{
    __shared__ float As[BK][BM + 4];  // padded to dodge store conflicts
    __shared__ float Bs[BK][BN];

    const int tid = threadIdx.x;
    const int bx = blockIdx.x, by = blockIdx.y;
    const int tx = tid & 15, ty = tid >> 4;

    // ---- A-tile load mapping: 512 float4 per tile, 2 per thread ----
    const int arow = tid >> 2;   // 0..63 (second load handles +64)
    const int ac4  = tid & 3;    // which float4 along K (0..3)
    int gr0 = by * BM + arow;
    int gr1 = gr0 + 64;
    if (GATHER) { gr0 = gidx[gr0]; gr1 = gidx[gr1]; }
    const float* Aptr0 = A + (size_t)gr0 * K + ac4 * 4;
    const float* Aptr1 = A + (size_t)gr1 * K + ac4 * 4;

    // ---- B-tile load mapping: 512 float4 per tile, 2 per thread ----
    const int brow = tid >> 5;   // 0..7 (second load handles +8)
    const int bc4  = tid & 31;
    const float* Bptr = B + (size_t)brow * N + bx * BN + bc4 * 4;

    float acc[TM][TN];
    #pragma unroll
    for (int i = 0; i < TM; i++)
        #pragma unroll
        for (int j = 0; j < TN; j++) acc[i][j] = 0.f;

    for (int kt = 0; kt < K; kt += BK) {
        float4 a0 = *(const float4*)(Aptr0 + kt);
        float4 a1 = *(const float4*)(Aptr1 + kt);
        float4 b0 = *(const float4*)(Bptr + (size_t)kt * N);
        float4 b1 = *(const float4*)(Bptr + (size_t)(kt + 8) * N);

        __syncthreads();  // previous compute done before overwrite

        As[ac4 * 4 + 0][arow]      = a0.x;
        As[ac4 * 4 + 1][arow]      = a0.y;
        As[ac4 * 4 + 2][arow]      = a0.z;
        As[ac4 * 4 + 3][arow]      = a0.w;
        As[ac4 * 4 + 0][arow + 64] = a1.x;
        As[ac4 * 4 + 1][arow + 64] = a1.y;
        As[ac4 * 4 + 2][arow + 64] = a1.z;
        As[ac4 * 4 + 3][arow + 64] = a1.w;
        *(float4*)&Bs[brow    ][bc4 * 4] = b0;
        *(float4*)&Bs[brow + 8][bc4 * 4] = b1;

        __syncthreads();

        #pragma unroll
        for (int k = 0; k < BK; k++) {
            float ra[TM], rb[TN];
            #pragma unroll
            for (int i = 0; i < TM; i++) ra[i] = As[k][ty * TM + i];
            #pragma unroll
            for (int j = 0; j < TN; j++) rb[j] = Bs[k][tx * TN + j];
            #pragma unroll
            for (int i = 0; i < TM; i++)
                #pragma unroll
                for (int j = 0; j < TN; j++)
                    acc[i][j] += ra[i] * rb[j];
        }
    }

    #pragma unroll
    for (int i = 0; i < TM; i++) {
        int row = by * BM + ty * TM + i;
        float* Cp = C + (size_t)row * N + bx * BN + tx * TN;
        *(float4*)(Cp)     = make_float4(acc[i][0], acc[i][1], acc[i][2], acc[i][3]);
        *(float4*)(Cp + 4) = make_float4(acc[i][4], acc[i][5], acc[i][6], acc[i][7]);
    }
}

// ============================================================================
// RoPE-style mix (in place on g_qkv, permuted order):
//   qr = q*cos + k*sin ; kr = k*cos - q*sin ; cos/sin indexed by ORIGINAL token
// ============================================================================
__global__ void rope_kernel(float* __restrict__ qkv,
                            const float* __restrict__ cosp,
                            const float* __restrict__ sinp,
                            const int* __restrict__ win)
{
    long idx = (long)blockIdx.x * blockDim.x + threadIdx.x;  // over S*C
    if (idx >= (long)S_TOK * C_DIM) return;
    int s = (int)(idx / C_DIM);
    int c = (int)(idx % C_DIM);
    int d = c % D_HEAD;
    int tok = win[s];
    float cv = cosp[(size_t)tok * D_HEAD + d];
    float sv = sinp[(size_t)tok * D_HEAD + d];
    size_t base = (size_t)s * C3;
    float q = qkv[base + c];
    float k = qkv[base + C_DIM + c];
    qkv[base + c]         = q * cv + k * sv;
    qkv[base + C_DIM + c] = k * cv - q * sv;
}

// ============================================================================
// Windowed attention: 16-token blocks, per head. One CTA per (block, head).
// Epilogue scatters rows back to ORIGINAL token order (inverse permutation).
// ============================================================================
__global__ __launch_bounds__(256)
void attn_kernel(const float* __restrict__ qkv, float* __restrict__ y,
                 const int* __restrict__ win)
{
    const int b = blockIdx.x >> 4;   // window block
    const int h = blockIdx.x & 15;   // head

    __shared__ float qs[BLK][D_HEAD + 1];
    __shared__ float ks[BLK][D_HEAD + 1];
    __shared__ float vs[BLK][D_HEAD + 1];
    __shared__ float att[BLK][BLK + 1];

    const int tid = threadIdx.x;

    // load q/k/v tiles (16 x 80 each)
    for (int t = tid; t < BLK * D_HEAD; t += 256) {
        int i = t / D_HEAD, d = t % D_HEAD;
        size_t base = (size_t)(b * BLK + i) * C3 + (size_t)h * D_HEAD + d;
        qs[i][d] = qkv[base];
        ks[i][d] = qkv[base + C_DIM];
        vs[i][d] = qkv[base + 2 * C_DIM];
    }
    __syncthreads();

    // scores: thread (i,j) computes q_i . k_j
    {
        int i = tid >> 4, j = tid & 15;
        float s = 0.f;
        #pragma unroll
        for (int d = 0; d < D_HEAD; d++) s += qs[i][d] * ks[j][d];
        att[i][j] = s * 0.11180339887498949f;   // 1/sqrt(80)
    }
    __syncthreads();

    // softmax per row (tiny: 16 rows x 16 cols)
    if (tid < BLK) {
        float m = -1e30f;
        #pragma unroll
        for (int j = 0; j < BLK; j++) m = fmaxf(m, att[tid][j]);
        float sum = 0.f;
        #pragma unroll
        for (int j = 0; j < BLK; j++) {
            float e = __expf(att[tid][j] - m);
            att[tid][j] = e;
            sum += e;
        }
        float inv = 1.f / sum;
        #pragma unroll
        for (int j = 0; j < BLK; j++) att[tid][j] *= inv;
    }
    __syncthreads();

    // out[i][d] = sum_j att[i][j] * v[j][d]; scatter row i -> token win[b*16+i]
    for (int t = tid; t < BLK * D_HEAD; t += 256) {
        int i = t / D_HEAD, d = t % D_HEAD;
        float acc = 0.f;
        #pragma unroll
        for (int j = 0; j < BLK; j++) acc += att[i][j] * vs[j][d];
        int tok = win[b * BLK + i];
        y[(size_t)tok * C_DIM + (size_t)h * D_HEAD + d] = acc;
    }
}

// ============================================================================
extern "C" void kernel_launch(void* const* d_in, const int* in_sizes, int n_in,
                              void* d_out, int out_size)
{
    const float* x     = (const float*)d_in[0];
    const float* cosp  = (const float*)d_in[1];
    const float* sinp  = (const float*)d_in[2];
    const float* Wqkv  = (const float*)d_in[3];
    const float* Wproj = (const float*)d_in[4];
    const int*   win   = (const int*)  d_in[5];
    float* out = (float*)d_out;

    float *qkv_ptr, *y_ptr;
    cudaGetSymbolAddress((void**)&qkv_ptr, g_qkv);
    cudaGetSymbolAddress((void**)&y_ptr,   g_y);

    // 1) QKV GEMM with fused gather: g_qkv[s] = x[win[s]] @ W_qkv
    {
        dim3 grid(C3 / BN, S_TOK / BM);
        sgemm_kernel<true><<<grid, 256>>>(x, Wqkv, qkv_ptr, win,
                                          S_TOK, C3, C_DIM);
    }

    // 2) RoPE mix in place
    {
        long total = (long)S_TOK * C_DIM;
        int blocks = (int)((total + 255) / 256);
        rope_kernel<<<blocks, 256>>>(qkv_ptr, cosp, sinp, win);
    }

    // 3) Windowed attention + inverse-permutation scatter into g_y
    {
        attn_kernel<<<NBLK * H_HEADS, 256>>>(qkv_ptr, y_ptr, win);
    }

    // 4) Output projection: out = g_y @ W_proj
    {
        dim3 grid(C_DIM / BN, S_TOK / BM);
        sgemm_kernel<false><<<grid, 256>>>(y_ptr, Wproj, out, nullptr,
                                           S_TOK, C_DIM, C_DIM);
    }
}

// round 2
// speedup vs baseline: 2.1654x; 2.1654x over previous
#include <cuda_runtime.h>
#include <math.h>
#include <stdint.h>

// Problem constants (fixed by dataset)
#define S_TOK   16384
#define C_DIM   1280
#define C3      3840
#define D_HEAD  80
#define H_HEADS 16
#define BLK     16
#define NBLK    (S_TOK / BLK)   // 1024

// Scratch (allocation-free rule: __device__ globals)
__device__ float g_qkv[(size_t)S_TOK * C3];    // permuted-order QKV
__device__ float g_y  [(size_t)S_TOK * C_DIM]; // attention out, ORIGINAL order

// ============================================================================
// TF32 tensor-core GEMM: C[M,N] = A[M,K] @ B[K,N]
//   - mma.sync.aligned.m16n8k8.row.col.f32.tf32.tf32.f32
//   - 128x128x16 CTA tile, 256 threads (8 warps as 4x2), warp tile 32x64
//   - GATHER: logical A row m reads physical row gidx[m]
// ============================================================================
#define BM 128
#define BN 128
#define BK 16
#define APAD 12   // smem row stride BM+12: LDS frags conflict-free, STS <=2-way
#define BPAD 12

__device__ __forceinline__ uint32_t f2tf(float f) {
    uint32_t r;
    asm("cvt.rna.tf32.f32 %0, %1;" : "=r"(r) : "f"(f));
    return r;
}

__device__ __forceinline__ void mma_tf32(float* d, const uint32_t* a, const uint32_t* b) {
    asm volatile(
        "mma.sync.aligned.m16n8k8.row.col.f32.tf32.tf32.f32 "
        "{%0,%1,%2,%3}, {%4,%5,%6,%7}, {%8,%9}, {%0,%1,%2,%3};"
        : "+f"(d[0]), "+f"(d[1]), "+f"(d[2]), "+f"(d[3])
        : "r"(a[0]), "r"(a[1]), "r"(a[2]), "r"(a[3]),
          "r"(b[0]), "r"(b[1]));
}

template<bool GATHER>
__global__ __launch_bounds__(256)
void mma_gemm_kernel(const float* __restrict__ A, const float* __restrict__ B,
                     float* __restrict__ C, const int* __restrict__ gidx,
                     int M, int N, int K)
{
    __shared__ uint32_t As[BK][BM + APAD];
    __shared__ uint32_t Bs[BK][BN + BPAD];

    const int tid  = threadIdx.x;
    const int bx   = blockIdx.x, by = blockIdx.y;
    const int warp = tid >> 5, lane = tid & 31;
    const int wm   = warp >> 1, wn = warp & 1;   // 4 x 2 warp grid
    const int g    = lane >> 2, t = lane & 3;    // mma groupID / threadID

    // ---- A global->smem mapping: 2 float4 per thread (rows arow, arow+64) ----
    const int arow = tid >> 2;        // 0..63
    const int ak   = (tid & 3) * 4;   // k offset of this float4
    int gr0 = by * BM + arow;
    int gr1 = gr0 + 64;
    if (GATHER) { gr0 = gidx[gr0]; gr1 = gidx[gr1]; }
    const float* Ap0 = A + (size_t)gr0 * K + ak;
    const float* Ap1 = A + (size_t)gr1 * K + ak;

    // ---- B global->smem mapping: 2 float4 per thread (k rows bk, bk+8) ----
    const int bk = tid >> 5;          // 0..7
    const int bn = (tid & 31) * 4;
    const float* Bp = B + (size_t)bk * N + bx * BN + bn;

    float acc[2][8][4];
    #pragma unroll
    for (int mt = 0; mt < 2; mt++)
        #pragma unroll
        for (int nt = 0; nt < 8; nt++)
            #pragma unroll
            for (int i = 0; i < 4; i++) acc[mt][nt][i] = 0.f;

    // prefetch tile 0
    float4 a0 = *(const float4*)(Ap0);
    float4 a1 = *(const float4*)(Ap1);
    float4 b0 = *(const float4*)(Bp);
    float4 b1 = *(const float4*)(Bp + (size_t)8 * N);

    for (int kt = 0; kt < K; kt += BK) {
        __syncthreads();
        // store staged tile (convert fp32 -> tf32 once here)
        As[ak + 0][arow]      = f2tf(a0.x);
        As[ak + 1][arow]      = f2tf(a0.y);
        As[ak + 2][arow]      = f2tf(a0.z);
        As[ak + 3][arow]      = f2tf(a0.w);
        As[ak + 0][arow + 64] = f2tf(a1.x);
        As[ak + 1][arow + 64] = f2tf(a1.y);
        As[ak + 2][arow + 64] = f2tf(a1.z);
        As[ak + 3][arow + 64] = f2tf(a1.w);
        {
            uint4 v0 = make_uint4(f2tf(b0.x), f2tf(b0.y), f2tf(b0.z), f2tf(b0.w));
            uint4 v1 = make_uint4(f2tf(b1.x), f2tf(b1.y), f2tf(b1.z), f2tf(b1.w));
            *(uint4*)&Bs[bk][bn]     = v0;
            *(uint4*)&Bs[bk + 8][bn] = v1;
        }
        __syncthreads();

        // stage next tile while computing this one
        if (kt + BK < K) {
            a0 = *(const float4*)(Ap0 + kt + BK);
            a1 = *(const float4*)(Ap1 + kt + BK);
            b0 = *(const float4*)(Bp + (size_t)(kt + BK) * N);
            b1 = *(const float4*)(Bp + (size_t)(kt + BK + 8) * N);
        }

        #pragma unroll
        for (int ks = 0; ks < 2; ks++) {       // two k8 steps per BK=16
            const int k0 = ks * 8;
            uint32_t af[2][4];
            #pragma unroll
            for (int mt = 0; mt < 2; mt++) {
                int m = wm * 32 + mt * 16 + g;
                af[mt][0] = As[k0 + t][m];
                af[mt][1] = As[k0 + t][m + 8];
                af[mt][2] = As[k0 + t + 4][m];
                af[mt][3] = As[k0 + t + 4][m + 8];
            }
            uint32_t bf[8][2];
            #pragma unroll
            for (int nt = 0; nt < 8; nt++) {
                int n = wn * 64 + nt * 8 + g;
                bf[nt][0] = Bs[k0 + t][n];
                bf[nt][1] = Bs[k0 + t + 4][n];
            }
            #pragma unroll
            for (int mt = 0; mt < 2; mt++)
                #pragma unroll
                for (int nt = 0; nt < 8; nt++)
                    mma_tf32(acc[mt][nt], af[mt], bf[nt]);
        }
    }

    // epilogue: D fragment layout -> C
    #pragma unroll
    for (int mt = 0; mt < 2; mt++) {
        int row0 = by * BM + wm * 32 + mt * 16 + g;
        #pragma unroll
        for (int nt = 0; nt < 8; nt++) {
            int col = bx * BN + wn * 64 + nt * 8 + t * 2;
            *(float2*)(C + (size_t)row0 * N + col) =
                make_float2(acc[mt][nt][0], acc[mt][nt][1]);
            *(float2*)(C + (size_t)(row0 + 8) * N + col) =
                make_float2(acc[mt][nt][2], acc[mt][nt][3]);
        }
    }
}

// ============================================================================
// Windowed attention with FUSED RoPE on load + inverse-permutation scatter.
// One CTA per (window block, head). 16x16 scores, D=80, fp32.
// ============================================================================
__global__ __launch_bounds__(256)
void attn_kernel(const float* __restrict__ qkv, float* __restrict__ y,
                 const int* __restrict__ win,
                 const float* __restrict__ cosp, const float* __restrict__ sinp)
{
    const int b = blockIdx.x >> 4;   // window block
    const int h = blockIdx.x & 15;   // head

    __shared__ float qs[BLK][D_HEAD + 1];
    __shared__ float ks[BLK][D_HEAD + 1];
    __shared__ float vs[BLK][D_HEAD + 1];
    __shared__ float att[BLK][BLK + 1];
    __shared__ int   toks[BLK];

    const int tid = threadIdx.x;

    if (tid < BLK) toks[tid] = win[b * BLK + tid];
    __syncthreads();

    // load q/k/v tiles, applying RoPE mix to q,k on the fly
    for (int tdx = tid; tdx < BLK * D_HEAD; tdx += 256) {
        int i = tdx / D_HEAD, d = tdx % D_HEAD;
        size_t base = (size_t)(b * BLK + i) * C3 + (size_t)h * D_HEAD + d;
        float q = qkv[base];
        float k = qkv[base + C_DIM];
        float v = qkv[base + 2 * C_DIM];
        int tok = toks[i];
        float cv = cosp[(size_t)tok * D_HEAD + d];
        float sv = sinp[(size_t)tok * D_HEAD + d];
        qs[i][d] = q * cv + k * sv;
        ks[i][d] = k * cv - q * sv;
        vs[i][d] = v;
    }
    __syncthreads();

    // scores: thread (i,j) computes q_i . k_j
    {
        int i = tid >> 4, j = tid & 15;
        float s = 0.f;
        #pragma unroll
        for (int d = 0; d < D_HEAD; d++) s += qs[i][d] * ks[j][d];
        att[i][j] = s * 0.11180339887498949f;   // 1/sqrt(80)
    }
    __syncthreads();

    // softmax per row
    if (tid < BLK) {
        float m = -1e30f;
        #pragma unroll
        for (int j = 0; j < BLK; j++) m = fmaxf(m, att[tid][j]);
        float sum = 0.f;
        #pragma unroll
        for (int j = 0; j < BLK; j++) {
            float e = __expf(att[tid][j] - m);
            att[tid][j] = e;
            sum += e;
        }
        float inv = 1.f / sum;
        #pragma unroll
        for (int j = 0; j < BLK; j++) att[tid][j] *= inv;
    }
    __syncthreads();

    // out[i][d] = sum_j att[i][j] * v[j][d]; scatter to ORIGINAL token order
    for (int tdx = tid; tdx < BLK * D_HEAD; tdx += 256) {
        int i = tdx / D_HEAD, d = tdx % D_HEAD;
        float a = 0.f;
        #pragma unroll
        for (int j = 0; j < BLK; j++) a += att[i][j] * vs[j][d];
        y[(size_t)toks[i] * C_DIM + (size_t)h * D_HEAD + d] = a;
    }
}

// ============================================================================
extern "C" void kernel_launch(void* const* d_in, const int* in_sizes, int n_in,
                              void* d_out, int out_size)
{
    const float* x     = (const float*)d_in[0];
    const float* cosp  = (const float*)d_in[1];
    const float* sinp  = (const float*)d_in[2];
    const float* Wqkv  = (const float*)d_in[3];
    const float* Wproj = (const float*)d_in[4];
    const int*   win   = (const int*)  d_in[5];
    float* out = (float*)d_out;

    float *qkv_ptr, *y_ptr;
    cudaGetSymbolAddress((void**)&qkv_ptr, g_qkv);
    cudaGetSymbolAddress((void**)&y_ptr,   g_y);

    // 1) QKV GEMM with fused gather: g_qkv[s] = x[win[s]] @ W_qkv
    {
        dim3 grid(C3 / BN, S_TOK / BM);
        mma_gemm_kernel<true><<<grid, 256>>>(x, Wqkv, qkv_ptr, win,
                                             S_TOK, C3, C_DIM);
    }

    // 2) Windowed attention (RoPE fused) + inverse-permutation scatter
    {
        attn_kernel<<<NBLK * H_HEADS, 256>>>(qkv_ptr, y_ptr, win, cosp, sinp);
    }

    // 3) Output projection: out = g_y @ W_proj
    {
        dim3 grid(C_DIM / BN, S_TOK / BM);
        mma_gemm_kernel<false><<<grid, 256>>>(y_ptr, Wproj, out, nullptr,
                                              S_TOK, C_DIM, C_DIM);
    }
}